// round 8
// baseline (speedup 1.0000x reference)
#include <cuda_runtime.h>
#include <cuda_bf16.h>
#include <math.h>
#include <stdint.h>

#define FULL 0xFFFFFFFFu

// ---------------- scratch (device globals; no allocation allowed) -------------
__device__ float g_ada[2 * 256];                 // [B, 2C] scale|shift
__device__ float g_y[2 * 64 * 64 * 128];         // LN output [rows, C]
__device__ float g_q[2 * 4 * 64 * 64 * 32];      // [B,n,H,W,d]
__device__ float g_k[2 * 4 * 64 * 64 * 32];
__device__ float g_v[2 * 4 * 64 * 64 * 32];
__device__ float g_att[2 * 64 * 64 * 128];       // [B,H,W,C]

__device__ __forceinline__ int nb_start(int i) {
    int s = i - 3;
    s = s < 0 ? 0 : s;
    return s > 57 ? 57 : s;   // L-K = 64-7
}

// ---- bf16 2-term split helpers ----------------------------------------------
__device__ __forceinline__ uint32_t bf16_split_pack(float x) {
    __nv_bfloat16 h = __float2bfloat16(x);
    float r = x - __bfloat162float(h);
    __nv_bfloat16 l = __float2bfloat16(r);
    return (uint32_t)__bfloat16_as_ushort(h) |
           ((uint32_t)__bfloat16_as_ushort(l) << 16);
}

__device__ __forceinline__ void mma_bf16(float* d, const uint32_t* a, const uint32_t* b) {
    asm("mma.sync.aligned.m16n8k16.row.col.f32.bf16.bf16.f32 "
        "{%0,%1,%2,%3}, {%4,%5,%6,%7}, {%8,%9}, {%0,%1,%2,%3};"
        : "+f"(d[0]), "+f"(d[1]), "+f"(d[2]), "+f"(d[3])
        : "r"(a[0]), "r"(a[1]), "r"(a[2]), "r"(a[3]), "r"(b[0]), "r"(b[1]));
}

// ---------------- kernel A: sinusoidal emb + silu + adaLN MLP -----------------
__global__ void adaln_kernel(const int* __restrict__ t,
                             const float* __restrict__ ln_w,
                             const float* __restrict__ ln_b) {
    __shared__ float s_silu[128];
    const int b = blockIdx.x;
    const int tid = threadIdx.x;
    const float tf = (float)t[b] * 40.0f;              // t/100*4000
    if (tid < 64) {
        float f = __expf(-(float)tid * (9.210340371976184f / 63.0f));
        float e = tf * f;
        float se = sinf(e), ce = cosf(e);
        s_silu[tid]      = se / (1.0f + __expf(-se));
        s_silu[tid + 64] = ce / (1.0f + __expf(-ce));
    }
    __syncthreads();
    const int j = tid;                                  // 0..255
    float acc = ln_b[j];
#pragma unroll 16
    for (int k = 0; k < 128; k++) acc += s_silu[k] * ln_w[k * 256 + j];
    g_ada[b * 256 + j] = acc;
}

// ---------------- kernel B: LayerNorm + modulate -> g_y -----------------------
__global__ void ln_kernel(const float* __restrict__ x) {
    const int tid = threadIdx.x;
    const int warp = tid >> 5, lane = tid & 31;
    const int row = blockIdx.x * 8 + warp;
    const int b = row >> 12;

    const float4 xv = *(const float4*)(x + row * 128 + lane * 4);
    float sum = xv.x + xv.y + xv.z + xv.w;
    float sq  = xv.x * xv.x + xv.y * xv.y + xv.z * xv.z + xv.w * xv.w;
#pragma unroll
    for (int o = 16; o; o >>= 1) {
        sum += __shfl_xor_sync(FULL, sum, o);
        sq  += __shfl_xor_sync(FULL, sq, o);
    }
    const float mean = sum * (1.0f / 128.0f);
    const float var  = sq * (1.0f / 128.0f) - mean * mean;
    const float rstd = rsqrtf(var + 1e-5f);

    const float4 sc = *(const float4*)(g_ada + b * 256 + lane * 4);
    const float4 sh = *(const float4*)(g_ada + b * 256 + 128 + lane * 4);
    float4 yv;
    yv.x = (xv.x - mean) * rstd * (1.0f + sc.x) + sh.x;
    yv.y = (xv.y - mean) * rstd * (1.0f + sc.y) + sh.y;
    yv.z = (xv.z - mean) * rstd * (1.0f + sc.z) + sh.z;
    yv.w = (xv.w - mean) * rstd * (1.0f + sc.w) + sh.w;
    *(float4*)(g_y + row * 128 + lane * 4) = yv;
}

// ---------------- kernel C: qkv GEMM (bf16x3 split tensor core) ---------------
// grid(128, 6), block(128) = 4 warps (2x2). tile 64x64, warp tile 32x32.
__global__ void __launch_bounds__(128)
qkv_gemm_tc(const float* __restrict__ W, const float* __restrict__ bias) {
    extern __shared__ uint32_t smem[];
    uint32_t* sa = smem;              // [64][132] packed bf16x2(hi,lo)
    uint32_t* sb = smem + 64 * 132;   // [128][72]

    const int tid = threadIdx.x;
    const int m0 = blockIdx.x * 64, n0 = blockIdx.y * 64;

    // stage A (split once)
#pragma unroll
    for (int r = 0; r < 16; r++) {
        const int id = tid + r * 128;
        const int row = id >> 5, j4 = id & 31;
        const float4 v = *(const float4*)(g_y + (m0 + row) * 128 + j4 * 4);
        uint32_t* p = sa + row * 132 + j4 * 4;
        p[0] = bf16_split_pack(v.x); p[1] = bf16_split_pack(v.y);
        p[2] = bf16_split_pack(v.z); p[3] = bf16_split_pack(v.w);
    }
    // stage B: W[k][n0+j], stride 384
#pragma unroll
    for (int r = 0; r < 16; r++) {
        const int id = tid + r * 128;
        const int kk = id >> 4, j4 = id & 15;
        const float4 v = *(const float4*)(W + kk * 384 + n0 + j4 * 4);
        uint32_t* p = sb + kk * 72 + j4 * 4;
        p[0] = bf16_split_pack(v.x); p[1] = bf16_split_pack(v.y);
        p[2] = bf16_split_pack(v.z); p[3] = bf16_split_pack(v.w);
    }
    __syncthreads();

    const int lane = tid & 31, warp = tid >> 5;
    const int wm = warp & 1, wn = warp >> 1;
    const int g = lane >> 2, tig = lane & 3;

    float d[2][4][4];
#pragma unroll
    for (int fm = 0; fm < 2; fm++)
#pragma unroll
        for (int fn = 0; fn < 4; fn++)
#pragma unroll
            for (int e = 0; e < 4; e++) d[fm][fn][e] = 0.0f;

#pragma unroll 4
    for (int k0 = 0; k0 < 128; k0 += 8) {
        uint32_t a[2][4];
#pragma unroll
        for (int fm = 0; fm < 2; fm++) {
            const int r = wm * 32 + fm * 16 + g;
            a[fm][0] = sa[(r    ) * 132 + k0 + tig];
            a[fm][1] = sa[(r + 8) * 132 + k0 + tig];
            a[fm][2] = sa[(r    ) * 132 + k0 + tig + 4];
            a[fm][3] = sa[(r + 8) * 132 + k0 + tig + 4];
        }
#pragma unroll
        for (int fn = 0; fn < 4; fn++) {
            const int c = wn * 32 + fn * 8 + g;
            const uint32_t p0 = sb[(k0 + tig    ) * 72 + c];
            const uint32_t p1 = sb[(k0 + tig + 4) * 72 + c];
            uint32_t bhh[2] = { __byte_perm(p0, p0, 0x1010),
                                __byte_perm(p1, p1, 0x1010) };
            uint32_t bl0[2] = { __byte_perm(p0, 0, 0x4432),
                                __byte_perm(p1, 0, 0x4432) };
#pragma unroll
            for (int fm = 0; fm < 2; fm++) {
                mma_bf16(d[fm][fn], a[fm], bhh);
                mma_bf16(d[fm][fn], a[fm], bl0);
            }
        }
    }

    // epilogue: scatter
    const float qscale = 0.17677669529663687f;   // 32^-0.5
#pragma unroll
    for (int fn = 0; fn < 4; fn++) {
        const int j0 = n0 + wn * 32 + fn * 8 + 2 * tig;
        const float bv0 = bias[j0], bv1 = bias[j0 + 1];
        const int which = j0 >> 7;
        const int rem = j0 & 127;
        const int nh = rem >> 5, dd = rem & 31;
#pragma unroll
        for (int fm = 0; fm < 2; fm++) {
#pragma unroll
            for (int half = 0; half < 2; half++) {
                const int row = m0 + wm * 32 + fm * 16 + g + half * 8;
                const int bb = row >> 12, hh = (row >> 6) & 63, ww = row & 63;
                const int idx = (((bb * 4 + nh) * 64 + hh) * 64 + ww) * 32 + dd;
                float v0 = d[fm][fn][half * 2 + 0] + bv0;
                float v1 = d[fm][fn][half * 2 + 1] + bv1;
                if (which == 0) {
                    v0 *= qscale; v1 *= qscale;
                    *(float2*)(g_q + idx) = make_float2(v0, v1);
                } else if (which == 1) {
                    *(float2*)(g_k + idx) = make_float2(v0, v1);
                } else {
                    *(float2*)(g_v + idx) = make_float2(v0, v1);
                }
            }
        }
    }
}

// ---------------- kernel D: 7x7 neighborhood attention, row-split -------------
// grid(32 h-tiles, 8 bn), block(256) = 2 h-rows x 64 w x 2 row-halves.
// Pair of threads per query: half 0 -> key rows a=0..3, half 1 -> a=4..6.
// Two-phase K->V smem reuse; swizzle j ^ ((w+a)&7) keeps pair threads
// (rows differing by 4) on distinct banks. Compute reads MUST use the
// (col + row) & 7 form (addition mod 8, NOT xor decomposition).
__global__ void __launch_bounds__(256, 2)
natten_kernel(const float* __restrict__ rpb) {
    extern __shared__ float smem_f[];
    float* skv = smem_f;              // 8*64*32 = 16384 floats = 64KB
    float* srpb = smem_f + 16384;     // 169

    const int tid = threadIdx.x;
    const int h0 = blockIdx.x * 2;
    const int bn = blockIdx.y;
    const int b = bn >> 2, n = bn & 3;
    const int base = bn * (64 * 64 * 32);

    const int hs0 = nb_start(h0);
    const int nrows = nb_start(h0 + 1) + 6 - hs0 + 1;   // 7 or 8
    const int nchunks = nrows * 512;                     // rows*64*8 float4s

    // ---- phase 1: stage K ----
    for (int i = tid; i < nchunks; i += 256) {
        const int a = i >> 9;
        const int rem = i & 511;
        const int w = rem >> 3, j = rem & 7;
        ((float4*)skv)[(a * 64 + w) * 8 + (j ^ ((w + a) & 7))] =
            *(const float4*)(g_k + base + (hs0 + a) * 2048 + w * 32 + j * 4);
    }
    for (int i = tid; i < 169; i += 256) srpb[i] = rpb[n * 169 + i];
    __syncthreads();

    const int qidx = tid >> 1;         // 0..127
    const int half = tid & 1;          // row-half: 0 -> a 0..3, 1 -> a 4..6
    const int ih = qidx >> 6;
    const int w = qidx & 63;
    const int h = h0 + ih;
    const int ws = nb_start(w);
    const int hs_q = nb_start(h);
    const int arow0 = hs_q - hs0;
    const int rbase = (hs_q - h + 6) * 13 + (ws - w + 6);
    const int a0 = half * 4;
    const int na = 4 - half;           // 4 or 3 rows

    float4 q4[8];
    {
        const int qoff = base + h * 2048 + w * 32;
#pragma unroll
        for (int j = 0; j < 8; j++) q4[j] = *(const float4*)(g_q + qoff + 4 * j);
    }

    float s[28];
#pragma unroll
    for (int aa = 0; aa < 4; aa++) {
        if (aa < na) {
            const int a = a0 + aa;
            const int row = arow0 + a;
#pragma unroll
            for (int c = 0; c < 7; c++) {
                const int col = ws + c;
                const float4* kp = ((const float4*)skv) + (row * 64 + col) * 8;
                const int sw = (col + row) & 7;
                float p0 = 0.f, p1 = 0.f, p2 = 0.f, p3 = 0.f;
#pragma unroll
                for (int j = 0; j < 8; j++) {
                    const float4 kv = kp[j ^ sw];
                    p0 += q4[j].x * kv.x;
                    p1 += q4[j].y * kv.y;
                    p2 += q4[j].z * kv.z;
                    p3 += q4[j].w * kv.w;
                }
                s[aa * 7 + c] = (p0 + p1) + (p2 + p3) + srpb[rbase + a * 13 + c];
            }
        }
    }

    // pair softmax
    float mloc = -INFINITY;
#pragma unroll
    for (int aa = 0; aa < 4; aa++)
        if (aa < na)
#pragma unroll
            for (int c = 0; c < 7; c++) mloc = fmaxf(mloc, s[aa * 7 + c]);
    const float m = fmaxf(mloc, __shfl_xor_sync(FULL, mloc, 1));

    float lloc = 0.f;
#pragma unroll
    for (int aa = 0; aa < 4; aa++)
        if (aa < na)
#pragma unroll
            for (int c = 0; c < 7; c++) {
                s[aa * 7 + c] = __expf(s[aa * 7 + c] - m);
                lloc += s[aa * 7 + c];
            }
    const float l = lloc + __shfl_xor_sync(FULL, lloc, 1);
    const float inv = 1.0f / l;

    __syncthreads();   // everyone done reading K

    // ---- phase 2: stage V into the same buffer ----
    for (int i = tid; i < nchunks; i += 256) {
        const int a = i >> 9;
        const int rem = i & 511;
        const int w_ = rem >> 3, j = rem & 7;
        ((float4*)skv)[(a * 64 + w_) * 8 + (j ^ ((w_ + a) & 7))] =
            *(const float4*)(g_v + base + (hs0 + a) * 2048 + w_ * 32 + j * 4);
    }
    __syncthreads();

    float4 acc4[8];
#pragma unroll
    for (int j = 0; j < 8; j++) acc4[j] = make_float4(0.f, 0.f, 0.f, 0.f);

#pragma unroll
    for (int aa = 0; aa < 4; aa++) {
        if (aa < na) {
            const int a = a0 + aa;
            const int row = arow0 + a;
            const float4* vp = ((const float4*)skv) + (row * 64 + ws) * 8;
#pragma unroll
            for (int c = 0; c < 7; c++) {
                const int col = ws + c;
                const int sw = (col + row) & 7;          // FIX: addition mod 8
                const float p = s[aa * 7 + c];
#pragma unroll
                for (int j = 0; j < 8; j++) {
                    const float4 vv = vp[c * 8 + (j ^ sw)];
                    acc4[j].x += p * vv.x;
                    acc4[j].y += p * vv.y;
                    acc4[j].z += p * vv.z;
                    acc4[j].w += p * vv.w;
                }
            }
        }
    }

    // combine pair partial sums: half 0 finalizes chunks 0..3, half 1 chunks 4..7.
    const int ob = ((b * 64 + h) * 64 + w) * 128 + n * 32;
#pragma unroll
    for (int j = 0; j < 4; j++) {
        const float4 send = half ? acc4[j] : acc4[j + 4];
        float4 recv;
        recv.x = __shfl_xor_sync(FULL, send.x, 1);
        recv.y = __shfl_xor_sync(FULL, send.y, 1);
        recv.z = __shfl_xor_sync(FULL, send.z, 1);
        recv.w = __shfl_xor_sync(FULL, send.w, 1);
        const float4 mine = half ? acc4[j + 4] : acc4[j];
        float4 o;
        o.x = (mine.x + recv.x) * inv;
        o.y = (mine.y + recv.y) * inv;
        o.z = (mine.z + recv.z) * inv;
        o.w = (mine.w + recv.w) * inv;
        *(float4*)(g_att + ob + (half * 4 + j) * 4) = o;
    }
}

// ---------------- kernel E: proj GEMM (bf16x3 split tensor core) --------------
__global__ void __launch_bounds__(128)
proj_gemm_tc(const float* __restrict__ W, const float* __restrict__ bias,
             float* __restrict__ out) {
    extern __shared__ uint32_t smem[];
    uint32_t* sa = smem;              // [64][132]
    uint32_t* sb = smem + 64 * 132;   // [128][72]

    const int tid = threadIdx.x;
    const int m0 = blockIdx.x * 64, n0 = blockIdx.y * 64;

#pragma unroll
    for (int r = 0; r < 16; r++) {
        const int id = tid + r * 128;
        const int row = id >> 5, j4 = id & 31;
        const float4 v = *(const float4*)(g_att + (m0 + row) * 128 + j4 * 4);
        uint32_t* p = sa + row * 132 + j4 * 4;
        p[0] = bf16_split_pack(v.x); p[1] = bf16_split_pack(v.y);
        p[2] = bf16_split_pack(v.z); p[3] = bf16_split_pack(v.w);
    }
#pragma unroll
    for (int r = 0; r < 16; r++) {
        const int id = tid + r * 128;
        const int kk = id >> 4, j4 = id & 15;
        const float4 v = *(const float4*)(W + kk * 128 + n0 + j4 * 4);
        uint32_t* p = sb + kk * 72 + j4 * 4;
        p[0] = bf16_split_pack(v.x); p[1] = bf16_split_pack(v.y);
        p[2] = bf16_split_pack(v.z); p[3] = bf16_split_pack(v.w);
    }
    __syncthreads();

    const int lane = tid & 31, warp = tid >> 5;
    const int wm = warp & 1, wn = warp >> 1;
    const int g = lane >> 2, tig = lane & 3;

    float d[2][4][4];
#pragma unroll
    for (int fm = 0; fm < 2; fm++)
#pragma unroll
        for (int fn = 0; fn < 4; fn++)
#pragma unroll
            for (int e = 0; e < 4; e++) d[fm][fn][e] = 0.0f;

#pragma unroll 4
    for (int k0 = 0; k0 < 128; k0 += 8) {
        uint32_t a[2][4];
#pragma unroll
        for (int fm = 0; fm < 2; fm++) {
            const int r = wm * 32 + fm * 16 + g;
            a[fm][0] = sa[(r    ) * 132 + k0 + tig];
            a[fm][1] = sa[(r + 8) * 132 + k0 + tig];
            a[fm][2] = sa[(r    ) * 132 + k0 + tig + 4];
            a[fm][3] = sa[(r + 8) * 132 + k0 + tig + 4];
        }
#pragma unroll
        for (int fn = 0; fn < 4; fn++) {
            const int c = wn * 32 + fn * 8 + g;
            const uint32_t p0 = sb[(k0 + tig    ) * 72 + c];
            const uint32_t p1 = sb[(k0 + tig + 4) * 72 + c];
            uint32_t bhh[2] = { __byte_perm(p0, p0, 0x1010),
                                __byte_perm(p1, p1, 0x1010) };
            uint32_t bl0[2] = { __byte_perm(p0, 0, 0x4432),
                                __byte_perm(p1, 0, 0x4432) };
#pragma unroll
            for (int fm = 0; fm < 2; fm++) {
                mma_bf16(d[fm][fn], a[fm], bhh);
                mma_bf16(d[fm][fn], a[fm], bl0);
            }
        }
    }

#pragma unroll
    for (int fn = 0; fn < 4; fn++) {
        const int j0 = n0 + wn * 32 + fn * 8 + 2 * tig;
        const float bv0 = bias[j0], bv1 = bias[j0 + 1];
#pragma unroll
        for (int fm = 0; fm < 2; fm++) {
#pragma unroll
            for (int half = 0; half < 2; half++) {
                const int row = m0 + wm * 32 + fm * 16 + g + half * 8;
                float v0 = d[fm][fn][half * 2 + 0] + bv0;
                float v1 = d[fm][fn][half * 2 + 1] + bv1;
                *(float2*)(out + row * 128 + j0) = make_float2(v0, v1);
            }
        }
    }
}

// ---------------- launch ------------------------------------------------------
extern "C" void kernel_launch(void* const* d_in, const int* in_sizes, int n_in,
                              void* d_out, int out_size) {
    const float* x      = (const float*)d_in[0];
    // d_in[1] = cond (unused)
    const int*   t      = (const int*)d_in[2];
    const float* ln_w   = (const float*)d_in[3];
    const float* ln_b   = (const float*)d_in[4];
    const float* qkv_w  = (const float*)d_in[5];
    const float* qkv_b  = (const float*)d_in[6];
    const float* rpb    = (const float*)d_in[7];
    const float* proj_w = (const float*)d_in[8];
    const float* proj_b = (const float*)d_in[9];
    float* out = (float*)d_out;

    const int gemm_smem = (64 * 132 + 128 * 72) * 4;   // 70,656 B
    const int natten_smem = (16384 + 176) * 4;         // 66,240 B
    cudaFuncSetAttribute(qkv_gemm_tc,
                         cudaFuncAttributeMaxDynamicSharedMemorySize, gemm_smem);
    cudaFuncSetAttribute(proj_gemm_tc,
                         cudaFuncAttributeMaxDynamicSharedMemorySize, gemm_smem);
    cudaFuncSetAttribute(natten_kernel,
                         cudaFuncAttributeMaxDynamicSharedMemorySize, natten_smem);

    adaln_kernel<<<2, 256>>>(t, ln_w, ln_b);
    ln_kernel<<<1024, 256>>>(x);
    qkv_gemm_tc<<<dim3(128, 6), 128, gemm_smem>>>(qkv_w, qkv_b);
    natten_kernel<<<dim3(32, 8), 256, natten_smem>>>(rpb);
    proj_gemm_tc<<<dim3(128, 2), 128, gemm_smem>>>(proj_w, proj_b, out);
}

// round 9
// speedup vs baseline: 1.0375x; 1.0375x over previous
#include <cuda_runtime.h>
#include <cuda_bf16.h>
#include <math.h>
#include <stdint.h>

#define FULL 0xFFFFFFFFu

// ---------------- scratch (device globals; no allocation allowed) -------------
__device__ float    g_ada[2 * 256];                // [B, 2C] scale|shift
__device__ uint32_t g_y[2 * 64 * 64 * 128];        // LN output, packed bf16(hi,lo)
__device__ uint32_t g_wq[128 * 384];               // qkv_w packed
__device__ uint32_t g_wp[128 * 128];               // proj_w packed
__device__ float    g_q[2 * 4 * 64 * 64 * 32];     // [B,n,H,W,d]
__device__ float    g_k[2 * 4 * 64 * 64 * 32];
__device__ float    g_v[2 * 4 * 64 * 64 * 32];
__device__ uint32_t g_att[2 * 64 * 64 * 128];      // attention out, packed bf16(hi,lo)

__device__ __forceinline__ int nb_start(int i) {
    int s = i - 3;
    s = s < 0 ? 0 : s;
    return s > 57 ? 57 : s;   // L-K = 64-7
}

// ---- bf16 2-term split helpers ----------------------------------------------
__device__ __forceinline__ uint32_t bf16_split_pack(float x) {
    __nv_bfloat16 h = __float2bfloat16(x);
    float r = x - __bfloat162float(h);
    __nv_bfloat16 l = __float2bfloat16(r);
    return (uint32_t)__bfloat16_as_ushort(h) |
           ((uint32_t)__bfloat16_as_ushort(l) << 16);
}

__device__ __forceinline__ void mma_bf16(float* d, const uint32_t* a, const uint32_t* b) {
    asm("mma.sync.aligned.m16n8k16.row.col.f32.bf16.bf16.f32 "
        "{%0,%1,%2,%3}, {%4,%5,%6,%7}, {%8,%9}, {%0,%1,%2,%3};"
        : "+f"(d[0]), "+f"(d[1]), "+f"(d[2]), "+f"(d[3])
        : "r"(a[0]), "r"(a[1]), "r"(a[2]), "r"(a[3]), "r"(b[0]), "r"(b[1]));
}

// ---------------- kernel P: pre-split weights (runs once per launch) ----------
__global__ void pack_w(const float* __restrict__ qkv_w,
                       const float* __restrict__ proj_w) {
    const int i = blockIdx.x * 256 + threadIdx.x;   // 0..65535
    if (i < 49152) g_wq[i] = bf16_split_pack(qkv_w[i]);
    else           g_wp[i - 49152] = bf16_split_pack(proj_w[i - 49152]);
}

// ---------------- kernel A: sinusoidal emb + silu + adaLN MLP -----------------
__global__ void adaln_kernel(const int* __restrict__ t,
                             const float* __restrict__ ln_w,
                             const float* __restrict__ ln_b) {
    __shared__ float s_silu[128];
    const int b = blockIdx.x;
    const int tid = threadIdx.x;
    const float tf = (float)t[b] * 40.0f;              // t/100*4000
    if (tid < 64) {
        float f = __expf(-(float)tid * (9.210340371976184f / 63.0f));
        float e = tf * f;
        float se = sinf(e), ce = cosf(e);
        s_silu[tid]      = se / (1.0f + __expf(-se));
        s_silu[tid + 64] = ce / (1.0f + __expf(-ce));
    }
    __syncthreads();
    const int j = tid;                                  // 0..255
    float acc = ln_b[j];
#pragma unroll 16
    for (int k = 0; k < 128; k++) acc += s_silu[k] * ln_w[k * 256 + j];
    g_ada[b * 256 + j] = acc;
}

// ---------------- kernel B: LayerNorm + modulate -> g_y (packed) --------------
__global__ void ln_kernel(const float* __restrict__ x) {
    const int tid = threadIdx.x;
    const int warp = tid >> 5, lane = tid & 31;
    const int row = blockIdx.x * 8 + warp;
    const int b = row >> 12;

    const float4 xv = *(const float4*)(x + row * 128 + lane * 4);
    float sum = xv.x + xv.y + xv.z + xv.w;
    float sq  = xv.x * xv.x + xv.y * xv.y + xv.z * xv.z + xv.w * xv.w;
#pragma unroll
    for (int o = 16; o; o >>= 1) {
        sum += __shfl_xor_sync(FULL, sum, o);
        sq  += __shfl_xor_sync(FULL, sq, o);
    }
    const float mean = sum * (1.0f / 128.0f);
    const float var  = sq * (1.0f / 128.0f) - mean * mean;
    const float rstd = rsqrtf(var + 1e-5f);

    const float4 sc = *(const float4*)(g_ada + b * 256 + lane * 4);
    const float4 sh = *(const float4*)(g_ada + b * 256 + 128 + lane * 4);
    uint4 pv;
    pv.x = bf16_split_pack((xv.x - mean) * rstd * (1.0f + sc.x) + sh.x);
    pv.y = bf16_split_pack((xv.y - mean) * rstd * (1.0f + sc.y) + sh.y);
    pv.z = bf16_split_pack((xv.z - mean) * rstd * (1.0f + sc.z) + sh.z);
    pv.w = bf16_split_pack((xv.w - mean) * rstd * (1.0f + sc.w) + sh.w);
    *(uint4*)(g_y + row * 128 + lane * 4) = pv;
}

// ---------------- kernel C: qkv GEMM (bf16x3 split tensor core) ---------------
// grid(128, 6), block(128) = 4 warps (2x2). tile 64x64, warp tile 32x32.
// Staging is pure copy: inputs already packed.
__global__ void __launch_bounds__(128)
qkv_gemm_tc(const float* __restrict__ bias) {
    extern __shared__ uint32_t smem[];
    uint32_t* sa = smem;              // [64][132] packed bf16x2(hi,lo)
    uint32_t* sb = smem + 64 * 132;   // [128][72]

    const int tid = threadIdx.x;
    const int m0 = blockIdx.x * 64, n0 = blockIdx.y * 64;

    // stage A (copy)
#pragma unroll
    for (int r = 0; r < 16; r++) {
        const int id = tid + r * 128;
        const int row = id >> 5, j4 = id & 31;
        *(uint4*)(sa + row * 132 + j4 * 4) =
            *(const uint4*)(g_y + (m0 + row) * 128 + j4 * 4);
    }
    // stage B (copy): g_wq[k][n0+j], stride 384
#pragma unroll
    for (int r = 0; r < 16; r++) {
        const int id = tid + r * 128;
        const int kk = id >> 4, j4 = id & 15;
        *(uint4*)(sb + kk * 72 + j4 * 4) =
            *(const uint4*)(g_wq + kk * 384 + n0 + j4 * 4);
    }
    __syncthreads();

    const int lane = tid & 31, warp = tid >> 5;
    const int wm = warp & 1, wn = warp >> 1;
    const int g = lane >> 2, tig = lane & 3;

    float d[2][4][4];
#pragma unroll
    for (int fm = 0; fm < 2; fm++)
#pragma unroll
        for (int fn = 0; fn < 4; fn++)
#pragma unroll
            for (int e = 0; e < 4; e++) d[fm][fn][e] = 0.0f;

#pragma unroll 4
    for (int k0 = 0; k0 < 128; k0 += 8) {
        uint32_t a[2][4];
#pragma unroll
        for (int fm = 0; fm < 2; fm++) {
            const int r = wm * 32 + fm * 16 + g;
            a[fm][0] = sa[(r    ) * 132 + k0 + tig];
            a[fm][1] = sa[(r + 8) * 132 + k0 + tig];
            a[fm][2] = sa[(r    ) * 132 + k0 + tig + 4];
            a[fm][3] = sa[(r + 8) * 132 + k0 + tig + 4];
        }
#pragma unroll
        for (int fn = 0; fn < 4; fn++) {
            const int c = wn * 32 + fn * 8 + g;
            const uint32_t p0 = sb[(k0 + tig    ) * 72 + c];
            const uint32_t p1 = sb[(k0 + tig + 4) * 72 + c];
            uint32_t bhh[2] = { __byte_perm(p0, p0, 0x1010),
                                __byte_perm(p1, p1, 0x1010) };
            uint32_t bl0[2] = { __byte_perm(p0, 0, 0x4432),
                                __byte_perm(p1, 0, 0x4432) };
#pragma unroll
            for (int fm = 0; fm < 2; fm++) {
                mma_bf16(d[fm][fn], a[fm], bhh);
                mma_bf16(d[fm][fn], a[fm], bl0);
            }
        }
    }

    // epilogue: scatter
    const float qscale = 0.17677669529663687f;   // 32^-0.5
#pragma unroll
    for (int fn = 0; fn < 4; fn++) {
        const int j0 = n0 + wn * 32 + fn * 8 + 2 * tig;
        const float bv0 = bias[j0], bv1 = bias[j0 + 1];
        const int which = j0 >> 7;
        const int rem = j0 & 127;
        const int nh = rem >> 5, dd = rem & 31;
#pragma unroll
        for (int fm = 0; fm < 2; fm++) {
#pragma unroll
            for (int half = 0; half < 2; half++) {
                const int row = m0 + wm * 32 + fm * 16 + g + half * 8;
                const int bb = row >> 12, hh = (row >> 6) & 63, ww = row & 63;
                const int idx = (((bb * 4 + nh) * 64 + hh) * 64 + ww) * 32 + dd;
                float v0 = d[fm][fn][half * 2 + 0] + bv0;
                float v1 = d[fm][fn][half * 2 + 1] + bv1;
                if (which == 0) {
                    v0 *= qscale; v1 *= qscale;
                    *(float2*)(g_q + idx) = make_float2(v0, v1);
                } else if (which == 1) {
                    *(float2*)(g_k + idx) = make_float2(v0, v1);
                } else {
                    *(float2*)(g_v + idx) = make_float2(v0, v1);
                }
            }
        }
    }
}

// ---------------- kernel D: 7x7 neighborhood attention, row-split -------------
// grid(32 h-tiles, 8 bn), block(256) = 2 h-rows x 64 w x 2 row-halves.
// Pair of threads per query: half 0 -> key rows a=0..3, half 1 -> a=4..6.
// Two-phase K->V smem reuse; swizzle j ^ ((w+a)&7); compute reads use the
// (col + row) & 7 form (addition mod 8, NOT xor decomposition).
// Epilogue packs output to bf16(hi,lo) for the proj GEMM.
__global__ void __launch_bounds__(256, 2)
natten_kernel(const float* __restrict__ rpb) {
    extern __shared__ float smem_f[];
    float* skv = smem_f;              // 8*64*32 = 16384 floats = 64KB
    float* srpb = smem_f + 16384;     // 169

    const int tid = threadIdx.x;
    const int h0 = blockIdx.x * 2;
    const int bn = blockIdx.y;
    const int b = bn >> 2, n = bn & 3;
    const int base = bn * (64 * 64 * 32);

    const int hs0 = nb_start(h0);
    const int nrows = nb_start(h0 + 1) + 6 - hs0 + 1;   // 7 or 8
    const int nchunks = nrows * 512;                     // rows*64*8 float4s

    // ---- phase 1: stage K ----
    for (int i = tid; i < nchunks; i += 256) {
        const int a = i >> 9;
        const int rem = i & 511;
        const int w = rem >> 3, j = rem & 7;
        ((float4*)skv)[(a * 64 + w) * 8 + (j ^ ((w + a) & 7))] =
            *(const float4*)(g_k + base + (hs0 + a) * 2048 + w * 32 + j * 4);
    }
    for (int i = tid; i < 169; i += 256) srpb[i] = rpb[n * 169 + i];
    __syncthreads();

    const int qidx = tid >> 1;         // 0..127
    const int half = tid & 1;          // row-half: 0 -> a 0..3, 1 -> a 4..6
    const int ih = qidx >> 6;
    const int w = qidx & 63;
    const int h = h0 + ih;
    const int ws = nb_start(w);
    const int hs_q = nb_start(h);
    const int arow0 = hs_q - hs0;
    const int rbase = (hs_q - h + 6) * 13 + (ws - w + 6);
    const int a0 = half * 4;
    const int na = 4 - half;           // 4 or 3 rows

    float4 q4[8];
    {
        const int qoff = base + h * 2048 + w * 32;
#pragma unroll
        for (int j = 0; j < 8; j++) q4[j] = *(const float4*)(g_q + qoff + 4 * j);
    }

    float s[28];
#pragma unroll
    for (int aa = 0; aa < 4; aa++) {
        if (aa < na) {
            const int a = a0 + aa;
            const int row = arow0 + a;
#pragma unroll
            for (int c = 0; c < 7; c++) {
                const int col = ws + c;
                const float4* kp = ((const float4*)skv) + (row * 64 + col) * 8;
                const int sw = (col + row) & 7;
                float p0 = 0.f, p1 = 0.f, p2 = 0.f, p3 = 0.f;
#pragma unroll
                for (int j = 0; j < 8; j++) {
                    const float4 kv = kp[j ^ sw];
                    p0 += q4[j].x * kv.x;
                    p1 += q4[j].y * kv.y;
                    p2 += q4[j].z * kv.z;
                    p3 += q4[j].w * kv.w;
                }
                s[aa * 7 + c] = (p0 + p1) + (p2 + p3) + srpb[rbase + a * 13 + c];
            }
        }
    }

    // pair softmax
    float mloc = -INFINITY;
#pragma unroll
    for (int aa = 0; aa < 4; aa++)
        if (aa < na)
#pragma unroll
            for (int c = 0; c < 7; c++) mloc = fmaxf(mloc, s[aa * 7 + c]);
    const float m = fmaxf(mloc, __shfl_xor_sync(FULL, mloc, 1));

    float lloc = 0.f;
#pragma unroll
    for (int aa = 0; aa < 4; aa++)
        if (aa < na)
#pragma unroll
            for (int c = 0; c < 7; c++) {
                s[aa * 7 + c] = __expf(s[aa * 7 + c] - m);
                lloc += s[aa * 7 + c];
            }
    const float l = lloc + __shfl_xor_sync(FULL, lloc, 1);
    const float inv = 1.0f / l;

    __syncthreads();   // everyone done reading K

    // ---- phase 2: stage V into the same buffer ----
    for (int i = tid; i < nchunks; i += 256) {
        const int a = i >> 9;
        const int rem = i & 511;
        const int w_ = rem >> 3, j = rem & 7;
        ((float4*)skv)[(a * 64 + w_) * 8 + (j ^ ((w_ + a) & 7))] =
            *(const float4*)(g_v + base + (hs0 + a) * 2048 + w_ * 32 + j * 4);
    }
    __syncthreads();

    float4 acc4[8];
#pragma unroll
    for (int j = 0; j < 8; j++) acc4[j] = make_float4(0.f, 0.f, 0.f, 0.f);

#pragma unroll
    for (int aa = 0; aa < 4; aa++) {
        if (aa < na) {
            const int a = a0 + aa;
            const int row = arow0 + a;
            const float4* vp = ((const float4*)skv) + (row * 64 + ws) * 8;
#pragma unroll
            for (int c = 0; c < 7; c++) {
                const int col = ws + c;
                const int sw = (col + row) & 7;          // addition mod 8
                const float p = s[aa * 7 + c];
#pragma unroll
                for (int j = 0; j < 8; j++) {
                    const float4 vv = vp[c * 8 + (j ^ sw)];
                    acc4[j].x += p * vv.x;
                    acc4[j].y += p * vv.y;
                    acc4[j].z += p * vv.z;
                    acc4[j].w += p * vv.w;
                }
            }
        }
    }

    // combine pair partial sums: half 0 finalizes chunks 0..3, half 1 chunks 4..7.
    const int ob = ((b * 64 + h) * 64 + w) * 128 + n * 32;
#pragma unroll
    for (int j = 0; j < 4; j++) {
        const float4 send = half ? acc4[j] : acc4[j + 4];
        float4 recv;
        recv.x = __shfl_xor_sync(FULL, send.x, 1);
        recv.y = __shfl_xor_sync(FULL, send.y, 1);
        recv.z = __shfl_xor_sync(FULL, send.z, 1);
        recv.w = __shfl_xor_sync(FULL, send.w, 1);
        const float4 mine = half ? acc4[j + 4] : acc4[j];
        uint4 o;
        o.x = bf16_split_pack((mine.x + recv.x) * inv);
        o.y = bf16_split_pack((mine.y + recv.y) * inv);
        o.z = bf16_split_pack((mine.z + recv.z) * inv);
        o.w = bf16_split_pack((mine.w + recv.w) * inv);
        *(uint4*)(g_att + ob + (half * 4 + j) * 4) = o;
    }
}

// ---------------- kernel E: proj GEMM (bf16x3 split tensor core) --------------
__global__ void __launch_bounds__(128)
proj_gemm_tc(const float* __restrict__ bias, float* __restrict__ out) {
    extern __shared__ uint32_t smem[];
    uint32_t* sa = smem;              // [64][132]
    uint32_t* sb = smem + 64 * 132;   // [128][72]

    const int tid = threadIdx.x;
    const int m0 = blockIdx.x * 64, n0 = blockIdx.y * 64;

#pragma unroll
    for (int r = 0; r < 16; r++) {
        const int id = tid + r * 128;
        const int row = id >> 5, j4 = id & 31;
        *(uint4*)(sa + row * 132 + j4 * 4) =
            *(const uint4*)(g_att + (m0 + row) * 128 + j4 * 4);
    }
#pragma unroll
    for (int r = 0; r < 16; r++) {
        const int id = tid + r * 128;
        const int kk = id >> 4, j4 = id & 15;
        *(uint4*)(sb + kk * 72 + j4 * 4) =
            *(const uint4*)(g_wp + kk * 128 + n0 + j4 * 4);
    }
    __syncthreads();

    const int lane = tid & 31, warp = tid >> 5;
    const int wm = warp & 1, wn = warp >> 1;
    const int g = lane >> 2, tig = lane & 3;

    float d[2][4][4];
#pragma unroll
    for (int fm = 0; fm < 2; fm++)
#pragma unroll
        for (int fn = 0; fn < 4; fn++)
#pragma unroll
            for (int e = 0; e < 4; e++) d[fm][fn][e] = 0.0f;

#pragma unroll 4
    for (int k0 = 0; k0 < 128; k0 += 8) {
        uint32_t a[2][4];
#pragma unroll
        for (int fm = 0; fm < 2; fm++) {
            const int r = wm * 32 + fm * 16 + g;
            a[fm][0] = sa[(r    ) * 132 + k0 + tig];
            a[fm][1] = sa[(r + 8) * 132 + k0 + tig];
            a[fm][2] = sa[(r    ) * 132 + k0 + tig + 4];
            a[fm][3] = sa[(r + 8) * 132 + k0 + tig + 4];
        }
#pragma unroll
        for (int fn = 0; fn < 4; fn++) {
            const int c = wn * 32 + fn * 8 + g;
            const uint32_t p0 = sb[(k0 + tig    ) * 72 + c];
            const uint32_t p1 = sb[(k0 + tig + 4) * 72 + c];
            uint32_t bhh[2] = { __byte_perm(p0, p0, 0x1010),
                                __byte_perm(p1, p1, 0x1010) };
            uint32_t bl0[2] = { __byte_perm(p0, 0, 0x4432),
                                __byte_perm(p1, 0, 0x4432) };
#pragma unroll
            for (int fm = 0; fm < 2; fm++) {
                mma_bf16(d[fm][fn], a[fm], bhh);
                mma_bf16(d[fm][fn], a[fm], bl0);
            }
        }
    }

#pragma unroll
    for (int fn = 0; fn < 4; fn++) {
        const int j0 = n0 + wn * 32 + fn * 8 + 2 * tig;
        const float bv0 = bias[j0], bv1 = bias[j0 + 1];
#pragma unroll
        for (int fm = 0; fm < 2; fm++) {
#pragma unroll
            for (int half = 0; half < 2; half++) {
                const int row = m0 + wm * 32 + fm * 16 + g + half * 8;
                float v0 = d[fm][fn][half * 2 + 0] + bv0;
                float v1 = d[fm][fn][half * 2 + 1] + bv1;
                *(float2*)(out + row * 128 + j0) = make_float2(v0, v1);
            }
        }
    }
}

// ---------------- launch ------------------------------------------------------
extern "C" void kernel_launch(void* const* d_in, const int* in_sizes, int n_in,
                              void* d_out, int out_size) {
    const float* x      = (const float*)d_in[0];
    // d_in[1] = cond (unused)
    const int*   t      = (const int*)d_in[2];
    const float* ln_w   = (const float*)d_in[3];
    const float* ln_b   = (const float*)d_in[4];
    const float* qkv_w  = (const float*)d_in[5];
    const float* qkv_b  = (const float*)d_in[6];
    const float* rpb    = (const float*)d_in[7];
    const float* proj_w = (const float*)d_in[8];
    const float* proj_b = (const float*)d_in[9];
    float* out = (float*)d_out;

    const int gemm_smem = (64 * 132 + 128 * 72) * 4;   // 70,656 B
    const int natten_smem = (16384 + 176) * 4;         // 66,240 B
    cudaFuncSetAttribute(qkv_gemm_tc,
                         cudaFuncAttributeMaxDynamicSharedMemorySize, gemm_smem);
    cudaFuncSetAttribute(proj_gemm_tc,
                         cudaFuncAttributeMaxDynamicSharedMemorySize, gemm_smem);
    cudaFuncSetAttribute(natten_kernel,
                         cudaFuncAttributeMaxDynamicSharedMemorySize, natten_smem);

    pack_w<<<256, 256>>>(qkv_w, proj_w);
    adaln_kernel<<<2, 256>>>(t, ln_w, ln_b);
    ln_kernel<<<1024, 256>>>(x);
    qkv_gemm_tc<<<dim3(128, 6), 128, gemm_smem>>>(qkv_b);
    natten_kernel<<<dim3(32, 8), 256, natten_smem>>>(rpb);
    proj_gemm_tc<<<dim3(128, 2), 128, gemm_smem>>>(proj_b, out);
}